// round 11
// baseline (speedup 1.0000x reference)
#include <cuda_runtime.h>
#include <cuda_bf16.h>
#include <cstdint>

// B=4, N=256, OBS=40, ACT=8, HEAD=8, DIM=32, T=256
// Algebra: nh/hid independent of broadcast index -> only column sums S_n,S_h;
// final gather at tgt -> ah needed at 4 rows.
// Tensor-core GEMMs: bf16 2-term split (3 mma/product, fp32 accum).
// Warp-autonomous 32-thread blocks, 16x32 C tile per warp, K=256 serial,
// 3-stage cp.async k32 pipeline, zero block barriers.
// Grids: E2 512, NE 512, colsum 1024 single-warp blocks (occupancy fix vs R8).

__device__ __align__(256) __nv_bfloat16 g_E1h[1024*256], g_E1l[1024*256];
__device__ __align__(256) __nv_bfloat16 g_We2Th[256*256], g_We2Tl[256*256];
__device__ __align__(256) __nv_bfloat16 g_WnTh[256*256],  g_WnTl[256*256];
__device__ __align__(256) __nv_bfloat16 g_WhTh[256*256],  g_WhTl[256*256];
__device__ __align__(256) __nv_bfloat16 g_adjh[256*256],  g_adjl[256*256];
__device__ __align__(256) __nv_bfloat16 g_E2fTh[4*256*256], g_E2fTl[4*256*256];
__device__ __align__(256) __nv_bfloat16 g_NEfh[1024*256], g_NEfl[1024*256];
__device__ float g_Sn[1024], g_Sh[1024], g_AH[1024];

__device__ __forceinline__ void bsplit(float v, __nv_bfloat16* ph, __nv_bfloat16* pl) {
    __nv_bfloat16 h = __float2bfloat16(v);
    *ph = h;
    *pl = __float2bfloat16(v - __bfloat162float(h));
}
__device__ __forceinline__ uint32_t packsplit(float v0, float v1, uint32_t* lo) {
    __nv_bfloat16 h0 = __float2bfloat16(v0), h1 = __float2bfloat16(v1);
    __nv_bfloat16 l0 = __float2bfloat16(v0 - __bfloat162float(h0));
    __nv_bfloat16 l1 = __float2bfloat16(v1 - __bfloat162float(h1));
    *lo = (uint32_t)*(uint16_t*)&l0 | ((uint32_t)*(uint16_t*)&l1 << 16);
    return (uint32_t)*(uint16_t*)&h0 | ((uint32_t)*(uint16_t*)&h1 << 16);
}
__device__ __forceinline__ void cp16(uint32_t dst, const void* src) {
    asm volatile("cp.async.ca.shared.global [%0], [%1], 16;\n" :: "r"(dst), "l"(src));
}
__device__ __forceinline__ void ldm_x4(uint32_t* r, uint32_t addr) {
    asm volatile("ldmatrix.sync.aligned.m8n8.x4.shared.b16 {%0,%1,%2,%3}, [%4];"
                 : "=r"(r[0]), "=r"(r[1]), "=r"(r[2]), "=r"(r[3]) : "r"(addr));
}
__device__ __forceinline__ void mma_bf16(float* d, const uint32_t* a, uint32_t b0, uint32_t b1) {
    asm volatile("mma.sync.aligned.m16n8k16.row.col.f32.bf16.bf16.f32 "
                 "{%0,%1,%2,%3}, {%4,%5,%6,%7}, {%8,%9}, {%0,%1,%2,%3};"
                 : "+f"(d[0]), "+f"(d[1]), "+f"(d[2]), "+f"(d[3])
                 : "r"(a[0]), "r"(a[1]), "r"(a[2]), "r"(a[3]), "r"(b0), "r"(b1));
}

// ---------------------------------------------------------------------------
__global__ void k_embed1(const float* __restrict__ x, const float* __restrict__ We1,
                         const float* __restrict__ be1) {
    __shared__ float xs[4][40];
    int r0 = blockIdx.x * 4;
    int tid = threadIdx.x;
    if (blockIdx.x == 0) {
#pragma unroll
        for (int i = 0; i < 4; i++) {
            g_Sn[i * 256 + tid] = 0.f;
            g_Sh[i * 256 + tid] = 0.f;
            g_AH[i * 256 + tid] = 0.f;
        }
    }
    if (tid < 160) {
        int rr = tid / 40, k = tid % 40;
        int row = r0 + rr;
        int b = row >> 8, i = row & 255;
        xs[rr][k] = x[b * 257 * 40 + i * 40 + k];
    }
    __syncthreads();
    float bias = be1[tid];
    float acc[4] = {bias, bias, bias, bias};
#pragma unroll
    for (int k = 0; k < 40; k++) {
        float w = We1[k * 256 + tid];
#pragma unroll
        for (int rr = 0; rr < 4; rr++) acc[rr] += xs[rr][k] * w;
    }
#pragma unroll
    for (int rr = 0; rr < 4; rr++) {
        float v = fmaxf(acc[rr], 0.f);
        size_t o = (size_t)(r0 + rr) * 256 + tid;
        bsplit(v, &g_E1h[o], &g_E1l[o]);
    }
}

// ---------------------------------------------------------------------------
__global__ void k_convW(const float* __restrict__ We2, const float* __restrict__ Wn,
                        const float* __restrict__ Wh, const float* __restrict__ adj) {
    __shared__ float ts[32][33];
    int z = blockIdx.z;
    int tx = threadIdx.x, ty = threadIdx.y;
    int n0 = blockIdx.x * 32, k0 = blockIdx.y * 32;
    const float* in = (z == 0) ? We2 : (z == 1) ? Wn : (z == 2) ? Wh : adj;
    __nv_bfloat16* oh = (z == 0) ? g_We2Th : (z == 1) ? g_WnTh : (z == 2) ? g_WhTh : g_adjh;
    __nv_bfloat16* ol = (z == 0) ? g_We2Tl : (z == 1) ? g_WnTl : (z == 2) ? g_WhTl : g_adjl;
    if (z < 3) {
        for (int r = ty; r < 32; r += 8)
            ts[r][tx] = in[(size_t)(k0 + r) * 256 + n0 + tx];
        __syncthreads();
        for (int r = ty; r < 32; r += 8) {
            float v = ts[tx][r];
            size_t o = (size_t)(n0 + r) * 256 + k0 + tx;
            bsplit(v, &oh[o], &ol[o]);
        }
    } else {
        for (int r = ty; r < 32; r += 8) {
            size_t o = (size_t)(k0 + r) * 256 + n0 + tx;
            bsplit(in[o], &oh[o], &ol[o]);
        }
    }
}

// ---------------------------------------------------------------------------
// Warp GEMM: C[16x32] = A[16x256] @ B[256x32] (B stored [n][k]), bf16 split.
// MODE 0: E2 -> relu(+be2) -> E2fT (transposed split).  grid (8,64)
// MODE 1: NE = adj@E2fT[b] -> NEf (split).              grid (8,16,4)
// MODE 2: colsum relu(NEf@W+bias) -> S.                 grid (8,64,2) z: Wn/Wh
// smem halves layout per stage: Ah[16][40], Al[16][40], Bh[32][40], Bl[32][40]
#define ROWB 80                 // bytes per smem row (40 halves)
#define A_ARRB 1280             // 16*80
#define B_ARRB 2560             // 32*80
#define STGB 7680               // 2*A_ARRB + 2*B_ARRB

template <int MODE>
__global__ void __launch_bounds__(32) k_wg(const float* __restrict__ biasN,
                                           const float* __restrict__ biasH) {
    __shared__ __align__(16) __nv_bfloat16 sm[3 * STGB / 2];
    int lane = threadIdx.x;
    int row0 = blockIdx.y * 16, col0 = blockIdx.x * 32;

    const __nv_bfloat16 *pAh, *pAl, *pBh, *pBl;
    size_t bExtra = 0;
    if (MODE == 0) { pAh = g_E1h;  pAl = g_E1l;  pBh = g_We2Th; pBl = g_We2Tl; }
    if (MODE == 1) { pAh = g_adjh; pAl = g_adjl; pBh = g_E2fTh; pBl = g_E2fTl;
                     bExtra = (size_t)blockIdx.z * 65536; }
    if (MODE == 2) { pAh = g_NEfh; pAl = g_NEfl;
                     pBh = blockIdx.z ? g_WhTh : g_WnTh;
                     pBl = blockIdx.z ? g_WhTl : g_WnTl; }

    const __nv_bfloat16* srcA =
        ((lane < 16) ? pAh : pAl) + (size_t)(row0 + (lane & 15)) * 256;
    const __nv_bfloat16* srcBh = pBh + bExtra + (size_t)(col0 + lane) * 256;
    const __nv_bfloat16* srcBl = pBl + bExtra + (size_t)(col0 + lane) * 256;
    uint32_t sbase = (uint32_t)__cvta_generic_to_shared(&sm[0]);
    uint32_t dA = sbase + ((lane < 16) ? 0u : (uint32_t)A_ARRB) + (uint32_t)(lane & 15) * ROWB;
    uint32_t dBh = sbase + 2u * A_ARRB + (uint32_t)lane * ROWB;
    uint32_t dBl = dBh + B_ARRB;

#define LOAD_CHUNK(c)                                                          \
    {                                                                          \
        uint32_t stb = (uint32_t)(((c) % 3) * STGB);                           \
        const __nv_bfloat16* sa = srcA + (c) * 32;                             \
        const __nv_bfloat16* sh = srcBh + (c) * 32;                            \
        const __nv_bfloat16* sl = srcBl + (c) * 32;                            \
        cp16(dA + stb, sa); cp16(dA + stb + 16, sa + 8);                       \
        cp16(dA + stb + 32, sa + 16); cp16(dA + stb + 48, sa + 24);            \
        cp16(dBh + stb, sh); cp16(dBh + stb + 16, sh + 8);                     \
        cp16(dBh + stb + 32, sh + 16); cp16(dBh + stb + 48, sh + 24);          \
        cp16(dBl + stb, sl); cp16(dBl + stb + 16, sl + 8);                     \
        cp16(dBl + stb + 32, sl + 16); cp16(dBl + stb + 48, sl + 24);          \
        asm volatile("cp.async.commit_group;\n" ::);                           \
    }

    LOAD_CHUNK(0)
    LOAD_CHUNK(1)

    int aRow = lane & 15;
    int aCol = (lane >> 4) << 3;
    int bRow = ((lane >> 4) << 3) + (lane & 7);
    int bCol = lane & 8;

    float acc[4][4] = {};
    for (int c = 0; c < 8; c++) {
        if (c + 2 < 8) {
            LOAD_CHUNK(c + 2)
            asm volatile("cp.async.wait_group 2;\n" ::);
        } else if (c == 6) {
            asm volatile("cp.async.wait_group 1;\n" ::);
        } else {
            asm volatile("cp.async.wait_group 0;\n" ::);
        }
        __syncwarp();
        uint32_t stB = sbase + (uint32_t)((c % 3) * STGB);
#pragma unroll
        for (int ki = 0; ki < 2; ki++) {
            uint32_t ah[4], al[4], bh[2][4], bl[2][4];
            uint32_t aOff = (uint32_t)(aRow * ROWB + (ki * 16 + aCol) * 2);
            ldm_x4(ah, stB + aOff);
            ldm_x4(al, stB + A_ARRB + aOff);
            uint32_t bOff = (uint32_t)(bRow * ROWB + (ki * 16 + bCol) * 2);
            ldm_x4(bh[0], stB + 2 * A_ARRB + bOff);
            ldm_x4(bh[1], stB + 2 * A_ARRB + 16 * ROWB + bOff);
            ldm_x4(bl[0], stB + 2 * A_ARRB + B_ARRB + bOff);
            ldm_x4(bl[1], stB + 2 * A_ARRB + B_ARRB + 16 * ROWB + bOff);
#pragma unroll
            for (int ni = 0; ni < 4; ni++) {
                const uint32_t* BH = &bh[ni >> 1][(ni & 1) * 2];
                const uint32_t* BL = &bl[ni >> 1][(ni & 1) * 2];
                float* d = acc[ni];
                mma_bf16(d, ah, BH[0], BH[1]);
                mma_bf16(d, ah, BL[0], BL[1]);
                mma_bf16(d, al, BH[0], BH[1]);
            }
        }
    }
#undef LOAD_CHUNK

    float (*red)[33] = reinterpret_cast<float(*)[33]>(&sm[0]);
#pragma unroll
    for (int ni = 0; ni < 4; ni++)
#pragma unroll
        for (int r = 0; r < 4; r++)
            red[(lane >> 2) + ((r >> 1) << 3)]
               [ni * 8 + (lane & 3) * 2 + (r & 1)] = acc[ni][r];
    __syncwarp();

    if (MODE == 0) {
        int b = row0 >> 8, i0 = row0 & 255;
        float bv = biasN[col0 + lane];
        uint32_t wh[8], wl[8];
#pragma unroll
        for (int p = 0; p < 8; p++) {
            float v0 = fmaxf(red[2 * p][lane] + bv, 0.f);
            float v1 = fmaxf(red[2 * p + 1][lane] + bv, 0.f);
            wh[p] = packsplit(v0, v1, &wl[p]);
        }
        size_t o = (size_t)b * 65536 + (size_t)(col0 + lane) * 256 + i0;
        uint4* gh = (uint4*)(g_E2fTh + o);
        uint4* gl = (uint4*)(g_E2fTl + o);
        gh[0] = make_uint4(wh[0], wh[1], wh[2], wh[3]);
        gh[1] = make_uint4(wh[4], wh[5], wh[6], wh[7]);
        gl[0] = make_uint4(wl[0], wl[1], wl[2], wl[3]);
        gl[1] = make_uint4(wl[4], wl[5], wl[6], wl[7]);
    }
    if (MODE == 1) {
        int r = lane & 15, c0 = (lane >> 4) * 16;
        uint32_t wh[8], wl[8];
#pragma unroll
        for (int p = 0; p < 8; p++)
            wh[p] = packsplit(red[r][c0 + 2 * p], red[r][c0 + 2 * p + 1], &wl[p]);
        size_t o = (size_t)(blockIdx.z * 256 + row0 + r) * 256 + col0 + c0;
        uint4* gh = (uint4*)(g_NEfh + o);
        uint4* gl = (uint4*)(g_NEfl + o);
        gh[0] = make_uint4(wh[0], wh[1], wh[2], wh[3]);
        gh[1] = make_uint4(wh[4], wh[5], wh[6], wh[7]);
        gl[0] = make_uint4(wl[0], wl[1], wl[2], wl[3]);
        gl[1] = make_uint4(wl[4], wl[5], wl[6], wl[7]);
    }
    if (MODE == 2) {
        const float* bias = blockIdx.z ? biasH : biasN;
        float bv = bias[col0 + lane];
        float s = 0.f;
#pragma unroll
        for (int r = 0; r < 16; r++) s += fmaxf(red[r][lane] + bv, 0.f);
        float* S = blockIdx.z ? g_Sh : g_Sn;
        atomicAdd(&S[(row0 >> 8) * 256 + col0 + lane], s);
    }
}

// ---------------------------------------------------------------------------
__global__ void k_ah(const float* __restrict__ x, const float* __restrict__ Wl) {
    __shared__ float vs[64];
    int b = blockIdx.x >> 2, kseg = blockIdx.x & 3;
    int t = threadIdx.x;
    int tgt = (int)x[b * 257 * 40 + 256 * 40];
    if (t < 64) {
        size_t o = (size_t)b * 65536 + (size_t)(kseg * 64 + t) * 256 + tgt;
        vs[t] = __bfloat162float(g_E2fTh[o]) + __bfloat162float(g_E2fTl[o]);
    }
    __syncthreads();
    float acc = 0.f;
#pragma unroll 8
    for (int k = 0; k < 64; k++)
        acc += vs[k] * Wl[(kseg * 64 + k) * 256 + t];
    atomicAdd(&g_AH[b * 256 + t], acc);
}

// ---------------------------------------------------------------------------
__global__ void k_final(const float* __restrict__ bl, const float* __restrict__ Wa,
                        const float* __restrict__ ba, float* __restrict__ out) {
    __shared__ float od[32];
    int b = blockIdx.x, tid = threadIdx.x;
    int h = tid >> 5, d = tid & 31;
    int t = d * 8 + h;
    float ahv = fmaxf(g_AH[b * 256 + t] + bl[t], 0.f);
    float logit = ahv * g_Sn[b * 256 + t];
    float m = logit;
#pragma unroll
    for (int o = 16; o > 0; o >>= 1) m = fmaxf(m, __shfl_xor_sync(0xffffffffu, m, o));
    float e = expf(logit - m);
    float ssum = e;
#pragma unroll
    for (int o = 16; o > 0; o >>= 1) ssum += __shfl_xor_sync(0xffffffffu, ssum, o);
    float val = (e / ssum) * g_Sh[b * 256 + t] * 0.125f;
    if (tid < 32) od[tid] = 0.f;
    __syncthreads();
    atomicAdd(&od[d], val);
    __syncthreads();
    if (tid < 8) {
        float acc = ba[tid];
#pragma unroll
        for (int dd = 0; dd < 32; dd++) acc += od[dd] * Wa[dd * 8 + tid];
        out[b * 8 + tid] = acc;
    }
    (void)h;
}

// ---------------------------------------------------------------------------
extern "C" void kernel_launch(void* const* d_in, const int* in_sizes, int n_in,
                              void* d_out, int out_size) {
    const float* x   = (const float*)d_in[0];
    const float* adj = (const float*)d_in[1];
    const float* We1 = (const float*)d_in[2];
    const float* be1 = (const float*)d_in[3];
    const float* We2 = (const float*)d_in[4];
    const float* be2 = (const float*)d_in[5];
    const float* Wl  = (const float*)d_in[6];
    const float* bl  = (const float*)d_in[7];
    const float* Wn  = (const float*)d_in[8];
    const float* bn  = (const float*)d_in[9];
    const float* Wh  = (const float*)d_in[10];
    const float* bh  = (const float*)d_in[11];
    const float* Wa  = (const float*)d_in[12];
    const float* ba  = (const float*)d_in[13];
    float* out = (float*)d_out;

    k_embed1<<<256, 256>>>(x, We1, be1);
    k_convW<<<dim3(8, 8, 4), dim3(32, 8)>>>(We2, Wn, Wh, adj);
    k_wg<0><<<dim3(8, 64, 1), 32>>>(be2, be2);     // E2 -> E2fT (512 blocks)
    k_wg<1><<<dim3(8, 16, 4), 32>>>(nullptr, nullptr); // NE -> NEf (512 blocks)
    k_wg<2><<<dim3(8, 64, 2), 32>>>(bn, bh);       // S_n + S_h (1024 blocks)
    k_ah<<<16, 256>>>(x, Wl);
    k_final<<<4, 256>>>(bl, Wa, ba, out);

    (void)in_sizes; (void)n_in; (void)out_size;
}